// round 16
// baseline (speedup 1.0000x reference)
#include <cuda_runtime.h>
#include <cuda_bf16.h>
#include <cstdint>

#define TWO_N 8192
#define NHALF 4096
#define DDIM  256
#define BM 128
#define NCTA 148
#define NTHR 256             // 8 warps: 4(M) x 2(N), warp tile 32x64
#define CHUNK_BYTES 16384    // one [128 rows][128B] swizzled k-chunk
#define TILE_BYTES  65536    // 128 x 256 bf16
#define PSTRIDE 88           // per-row partial slots (64 main + 24 quarter)

__device__ __nv_bfloat16 g_znb[TWO_N * DDIM];
__device__ float g_p[(size_t)TWO_N * PSTRIDE];  // [row][88] partial exp-sums
__device__ float g_cdd[TWO_N];              // self dot per row
__device__ float g_cdp[TWO_N];              // positive-pair dot per row
__device__ float g_bs[64];                  // per-rowblock loss partial
__device__ int   g_cnt;                     // reducer counter (self-reset)
__device__ int   g_done;                    // sim-phase completion counter

#define L2E2 2.8853900817779268f    /* 2/ln2 : exp(2d) = 2^(d*L2E2) */

// ---------------------------------------------------------------- helpers --
__device__ __forceinline__ uint32_t smem_u32(const void* p) {
    uint32_t a;
    asm("{ .reg .u64 t; cvta.to.shared.u64 t, %1; cvt.u32.u64 %0, t; }"
        : "=r"(a) : "l"(p));
    return a;
}
__device__ __forceinline__ float ex2f(float x) {
    float y; asm("ex2.approx.f32 %0, %1;" : "=f"(y) : "f"(x)); return y;
}
#define CP_ASYNC16(sm, gp) \
    asm volatile("cp.async.cg.shared.global [%0], [%1], 16;" \
                 :: "r"(sm), "l"(gp) : "memory")
#define CP_COMMIT()  asm volatile("cp.async.commit_group;" ::: "memory")
#define CP_WAIT(n)   asm volatile("cp.async.wait_group %0;" :: "n"(n) : "memory")

__device__ __forceinline__ void ldsm_x4(uint32_t* r, uint32_t addr) {
    asm volatile("ldmatrix.sync.aligned.m8n8.x4.shared.b16 {%0,%1,%2,%3}, [%4];"
                 : "=r"(r[0]), "=r"(r[1]), "=r"(r[2]), "=r"(r[3]) : "r"(addr));
}
__device__ __forceinline__ void mma16816(float* c, const uint32_t* a,
                                         uint32_t b0, uint32_t b1) {
    asm volatile(
        "mma.sync.aligned.m16n8k16.row.col.f32.bf16.bf16.f32 "
        "{%0,%1,%2,%3}, {%4,%5,%6,%7}, {%8,%9}, {%0,%1,%2,%3};"
        : "+f"(c[0]), "+f"(c[1]), "+f"(c[2]), "+f"(c[3])
        : "r"(a[0]), "r"(a[1]), "r"(a[2]), "r"(a[3]), "r"(b0), "r"(b1));
}

// upper-triangle block decode in paired-strip order
__device__ __forceinline__ void bdecode(int g, int& I, int& J) {
    int p = g / 65, r = g - p * 65;
    if (r < 64 - p) { I = p;      J = p + r; }
    else            { I = 63 - p; J = I + (r - (64 - p)); }
}

// ---------------------------------------------------------------------------
// Kernel 1: L2-normalize rows -> bf16. 2 rows per warp (champion config).
// ---------------------------------------------------------------------------
__global__ void norm_kernel(const float* __restrict__ z1,
                            const float* __restrict__ z2) {
    int wid = threadIdx.x >> 5, lane = threadIdx.x & 31;
    int row0 = (blockIdx.x * 8 + wid) * 2;
    int row1 = row0 + 1;
    const float4* s0 = reinterpret_cast<const float4*>(
        (row0 < NHALF) ? (z1 + (size_t)row0 * DDIM)
                       : (z2 + (size_t)(row0 - NHALF) * DDIM));
    const float4* s1 = reinterpret_cast<const float4*>(
        (row1 < NHALF) ? (z1 + (size_t)row1 * DDIM)
                       : (z2 + (size_t)(row1 - NHALF) * DDIM));
    float4 a0 = s0[lane * 2], a1 = s0[lane * 2 + 1];
    float4 b0 = s1[lane * 2], b1 = s1[lane * 2 + 1];
    float sa = a0.x * a0.x + a0.y * a0.y + a0.z * a0.z + a0.w * a0.w
             + a1.x * a1.x + a1.y * a1.y + a1.z * a1.z + a1.w * a1.w;
    float sb = b0.x * b0.x + b0.y * b0.y + b0.z * b0.z + b0.w * b0.w
             + b1.x * b1.x + b1.y * b1.y + b1.z * b1.z + b1.w * b1.w;
#pragma unroll
    for (int o = 16; o; o >>= 1) {
        sa += __shfl_xor_sync(0xffffffffu, sa, o);
        sb += __shfl_xor_sync(0xffffffffu, sb, o);
    }
    float ia = 1.0f / fmaxf(sqrtf(sa), 1e-8f);
    float ib = 1.0f / fmaxf(sqrtf(sb), 1e-8f);
    uint4 pa, pb;
    asm("cvt.rn.bf16x2.f32 %0, %1, %2;" : "=r"(pa.x) : "f"(a0.y * ia), "f"(a0.x * ia));
    asm("cvt.rn.bf16x2.f32 %0, %1, %2;" : "=r"(pa.y) : "f"(a0.w * ia), "f"(a0.z * ia));
    asm("cvt.rn.bf16x2.f32 %0, %1, %2;" : "=r"(pa.z) : "f"(a1.y * ia), "f"(a1.x * ia));
    asm("cvt.rn.bf16x2.f32 %0, %1, %2;" : "=r"(pa.w) : "f"(a1.w * ia), "f"(a1.z * ia));
    asm("cvt.rn.bf16x2.f32 %0, %1, %2;" : "=r"(pb.x) : "f"(b0.y * ib), "f"(b0.x * ib));
    asm("cvt.rn.bf16x2.f32 %0, %1, %2;" : "=r"(pb.y) : "f"(b0.w * ib), "f"(b0.z * ib));
    asm("cvt.rn.bf16x2.f32 %0, %1, %2;" : "=r"(pb.z) : "f"(b1.y * ib), "f"(b1.x * ib));
    asm("cvt.rn.bf16x2.f32 %0, %1, %2;" : "=r"(pb.w) : "f"(b1.w * ib), "f"(b1.z * ib));
    reinterpret_cast<uint4*>(g_znb + (size_t)row0 * DDIM)[lane] = pa;
    reinterpret_cast<uint4*>(g_znb + (size_t)row1 * DDIM)[lane] = pb;
}

// ---------------------------------------------------------------------------
// tile loader: 128 rows x 256 bf16 -> swizzled k-chunks via cp.async
// ---------------------------------------------------------------------------
__device__ __forceinline__ void load_tile(uint32_t sdst, int rowblk, int tid) {
    const char* gsrc = (const char*)(g_znb + (size_t)rowblk * BM * DDIM);
#pragma unroll
    for (int i = 0; i < 16; i++) {
        int unit = i * NTHR + tid;           // row*32 + uu
        int row = unit >> 5, uu = unit & 31;
        uint32_t off = (uint32_t)(row * 128 + (uu & 7) * 16);
        off ^= (off >> 3) & 0x70;
        CP_ASYNC16(sdst + (uu >> 3) * CHUNK_BYTES + off, gsrc + unit * 16);
    }
}

// ---------------------------------------------------------------------------
// Kernel 2: symmetric HMMA GEMM (14 full blocks/CTA + 32 quarter-blocks),
// with the reduce phase folded into the tail of CTAs 0..63.
// ---------------------------------------------------------------------------
__global__ void __launch_bounds__(NTHR, 1) sim_kernel(float* __restrict__ out) {
    extern __shared__ char smem_raw[];
    char* sbase = (char*)(((uintptr_t)smem_raw + 1023) & ~(uintptr_t)1023);
    uint32_t sAu = smem_u32(sbase);              // A: 64 KB (single)
    uint32_t sBu = sAu + TILE_BYTES;             // B: 2 x 64 KB

    __shared__ float s_rs[2][BM];                // n-half rowsum partials
    __shared__ float s_cs[8][64];                // [mwarp*2+nhalf][col]

    int tid = threadIdx.x;
    int wid = tid >> 5, lane = tid & 31;
    int cta = blockIdx.x;
    int start = cta * 14;
    const int cnt = 14;

    int m_base = (wid >> 1) * 32;
    int n_base = (wid & 1) * 64;
    int mwarp = wid >> 1, nhalf = wid & 1;

    // ---- per-lane ldmatrix address pieces ----
    int rA0 = m_base + (lane & 15);
    int rA1 = rA0 + 16;
    uint32_t kaddA = ((lane >> 4) & 1) * 16;
    uint32_t rowA0 = (uint32_t)rA0 * 128, xA0 = (uint32_t)(rA0 & 7) << 4;
    uint32_t rowA1 = (uint32_t)rA1 * 128, xA1 = (uint32_t)(rA1 & 7) << 4;
    int rBb = n_base + (lane & 7) + ((lane & 16) >> 1);
    uint32_t kaddB = ((lane >> 3) & 1) * 16;
    uint32_t rowB[4], xB[4];
#pragma unroll
    for (int gI = 0; gI < 4; gI++) {
        int r = rBb + gI * 16;
        rowB[gI] = (uint32_t)r * 128;
        xB[gI] = (uint32_t)(r & 7) << 4;
    }
    int lrow[4];
#pragma unroll
    for (int s = 0; s < 4; s++)
        lrow[s] = m_base + (s >> 1) * 16 + (lane >> 2) + (s & 1) * 8;
    int lcb = n_base + (lane & 3) * 2;           // base local col of this lane

    float accA[2][8][4], accB[2][8][4];
    float rs[4] = {0.f, 0.f, 0.f, 0.f};
    float cs[8][2];
#pragma unroll
    for (int j = 0; j < 8; j++) { cs[j][0] = 0.f; cs[j][1] = 0.f; }
    int curI;

    auto flush_old = [&](int oI, int oJ) {
#pragma unroll
        for (int s2 = 0; s2 < 4; s2++) {
            float v = rs[s2];
            v += __shfl_xor_sync(0xffffffffu, v, 1);
            v += __shfl_xor_sync(0xffffffffu, v, 2);
            if ((lane & 3) == 0) s_rs[nhalf][lrow[s2]] = v;
        }
        if (oI != oJ) {
#pragma unroll
            for (int j = 0; j < 8; j++)
#pragma unroll
                for (int cb = 0; cb < 2; cb++) {
                    float v = cs[j][cb];
                    v += __shfl_xor_sync(0xffffffffu, v, 4);
                    v += __shfl_xor_sync(0xffffffffu, v, 8);
                    v += __shfl_xor_sync(0xffffffffu, v, 16);
                    if (lane < 4)
                        s_cs[mwarp * 2 + nhalf][j * 8 + lane * 2 + cb] = v;
                }
        }
        __syncthreads();
        if (tid < BM) {
            g_p[((size_t)oI * BM + tid) * PSTRIDE + oJ] =
                s_rs[0][tid] + s_rs[1][tid];
            if (oI != oJ) {
                int nh = tid >> 6, cc = tid & 63;
                g_p[((size_t)oJ * BM + tid) * PSTRIDE + oI] =
                    s_cs[nh][cc] + s_cs[2 + nh][cc] +
                    s_cs[4 + nh][cc] + s_cs[6 + nh][cc];
            }
        }
#pragma unroll
        for (int s2 = 0; s2 < 4; s2++) rs[s2] = 0.f;
#pragma unroll
        for (int j = 0; j < 8; j++) { cs[j][0] = 0.f; cs[j][1] = 0.f; }
    };

    auto run_block = [&](float (&acc)[2][8][4], float (&aold)[2][8][4],
                         int n, int oI, int oJ, bool do_old) {
        if (n + 1 < cnt) {
            int In, Jn; bdecode(start + n + 1, In, Jn);
            load_tile(sBu + ((n + 1) & 1) * TILE_BYTES, Jn, tid);
            CP_COMMIT();
            CP_WAIT(1);
        } else {
            CP_WAIT(0);
        }
        __syncthreads();

#pragma unroll
        for (int i = 0; i < 2; i++)
#pragma unroll
            for (int j = 0; j < 8; j++)
#pragma unroll
                for (int q = 0; q < 4; q++) acc[i][j][q] = 0.f;

        uint32_t bbase = sBu + (n & 1) * TILE_BYTES;
        bool isdiag = (oI == oJ);
        bool capb = do_old && (isdiag || oJ == oI + 32);

#pragma unroll
        for (int s = 0; s < 16; s++) {           // k = s*16
            uint32_t coff = (uint32_t)(s >> 2) * CHUNK_BYTES;
            uint32_t kbA = (uint32_t)(s & 3) * 32 + kaddA;
            uint32_t kbB = (uint32_t)(s & 3) * 32 + kaddB;
            uint32_t a0[4], a1[4], b[4][4];
            ldsm_x4(a0, sAu + coff + rowA0 + (kbA ^ xA0));
            ldsm_x4(a1, sAu + coff + rowA1 + (kbA ^ xA1));
#pragma unroll
            for (int gI = 0; gI < 4; gI++)
                ldsm_x4(b[gI], bbase + coff + rowB[gI] + (kbB ^ xB[gI]));

            // deferred epilogue chunk: element (ii, jj) of old block
            if (do_old) {
                const int ii = s >> 3, jj = s & 7;
#pragma unroll
                for (int q = 0; q < 4; q++) {
                    float d = aold[ii][jj][q];
                    float e = ex2f(d * L2E2);
                    rs[ii * 2 + (q >> 1)] += e;
                    cs[jj][q & 1] += e;
                    if (capb) {
                        int slot = ii * 2 + (q >> 1);
                        int lc = lcb + jj * 8 + (q & 1);
                        if (lc == lrow[slot]) {
                            int rg = oI * BM + lrow[slot];
                            if (isdiag) g_cdd[rg] = d;
                            else { g_cdp[rg] = d;
                                   g_cdp[oJ * BM + lrow[slot]] = d; }
                        }
                    }
                }
            }

#pragma unroll
            for (int j = 0; j < 8; j++) {
                uint32_t b0 = b[j >> 1][(j & 1) * 2];
                uint32_t b1 = b[j >> 1][(j & 1) * 2 + 1];
                mma16816(acc[0][j], a0, b0, b1);
                mma16816(acc[1][j], a1, b0, b1);
            }
        }
        __syncthreads();   // sA / sB[n&1] no longer read

        if (n + 1 < cnt) {
            int In, Jn; bdecode(start + n + 1, In, Jn);
            if (In != curI) { load_tile(sAu, In, tid); CP_COMMIT(); curI = In; }
        }
        if (do_old) flush_old(oI, oJ);
    };

    // ---- prologue ----
    int I0, J0; bdecode(start, I0, J0);
    load_tile(sAu, I0, tid); CP_COMMIT();
    load_tile(sBu, J0, tid); CP_COMMIT();
    curI = I0;

    bool useA = true;
    int pI = 0, pJ = 0;
#pragma unroll 1
    for (int n = 0; n < cnt; n++) {
        int I, J; bdecode(start + n, I, J);
        if (useA) run_block(accA, accB, n, pI, pJ, n > 0);
        else      run_block(accB, accA, n, pI, pJ, n > 0);
        useA = !useA; pI = I; pJ = J;
    }

    // ---- issue quarter-block loads early (overlap final epilogue) ----
    int qJ = 56 + (cta >> 2);
    if (cta < 32) {
        load_tile(sAu, 32, tid);
        load_tile(sBu, qJ, tid);
        CP_COMMIT();
    }

    // ---- final (non-interleaved) epilogue for the last full block ----
    {
        __syncthreads();
        bool isdiag = (pI == pJ);
        bool capb = isdiag || (pJ == pI + 32);
#pragma unroll
        for (int ii = 0; ii < 2; ii++)
#pragma unroll
            for (int jj = 0; jj < 8; jj++)
#pragma unroll
                for (int q = 0; q < 4; q++) {
                    float d = useA ? accB[ii][jj][q] : accA[ii][jj][q];
                    float e = ex2f(d * L2E2);
                    rs[ii * 2 + (q >> 1)] += e;
                    cs[jj][q & 1] += e;
                    if (capb) {
                        int slot = ii * 2 + (q >> 1);
                        int lc = lcb + jj * 8 + (q & 1);
                        if (lc == lrow[slot]) {
                            int rg = pI * BM + lrow[slot];
                            if (isdiag) g_cdd[rg] = d;
                            else { g_cdp[rg] = d;
                                   g_cdp[pJ * BM + lrow[slot]] = d; }
                        }
                    }
                }
        flush_old(pI, pJ);
    }

    // ---- quarter-block (CTAs 0..31): N=32 slice of block (32, qJ) ----
    if (cta < 32) {
        int qq = cta & 3;
        CP_WAIT(0);
        __syncthreads();

        int colbase = qq * 32 + nhalf * 16;      // quarter col base per n-warp
        int rBq = colbase + (lane & 7) + ((lane & 16) >> 1);
        uint32_t rowBq = (uint32_t)rBq * 128, xBq = (uint32_t)(rBq & 7) << 4;

        float qacc[2][2][4];
#pragma unroll
        for (int i = 0; i < 2; i++)
#pragma unroll
            for (int j = 0; j < 2; j++)
#pragma unroll
                for (int q = 0; q < 4; q++) qacc[i][j][q] = 0.f;

#pragma unroll
        for (int s = 0; s < 16; s++) {           // k = s*16
            uint32_t coff = (uint32_t)(s >> 2) * CHUNK_BYTES;
            uint32_t kbA = (uint32_t)(s & 3) * 32 + kaddA;
            uint32_t kbB = (uint32_t)(s & 3) * 32 + kaddB;
            uint32_t a0[4], a1[4], bq[4];
            ldsm_x4(a0, sAu + coff + rowA0 + (kbA ^ xA0));
            ldsm_x4(a1, sAu + coff + rowA1 + (kbA ^ xA1));
            ldsm_x4(bq, sBu + coff + rowBq + (kbB ^ xBq));
            mma16816(qacc[0][0], a0, bq[0], bq[1]);
            mma16816(qacc[0][1], a0, bq[2], bq[3]);
            mma16816(qacc[1][0], a1, bq[0], bq[1]);
            mma16816(qacc[1][1], a1, bq[2], bq[3]);
        }

        // epilogue: rowsums + colsums (no captures possible here)
        float qrs[4] = {0.f, 0.f, 0.f, 0.f};
        float qcs[2][2] = {{0.f, 0.f}, {0.f, 0.f}};
#pragma unroll
        for (int ii = 0; ii < 2; ii++)
#pragma unroll
            for (int jj = 0; jj < 2; jj++)
#pragma unroll
                for (int q = 0; q < 4; q++) {
                    float e = ex2f(qacc[ii][jj][q] * L2E2);
                    qrs[ii * 2 + (q >> 1)] += e;
                    qcs[jj][q & 1] += e;
                }
#pragma unroll
        for (int s2 = 0; s2 < 4; s2++) {
            float v = qrs[s2];
            v += __shfl_xor_sync(0xffffffffu, v, 1);
            v += __shfl_xor_sync(0xffffffffu, v, 2);
            if ((lane & 3) == 0) s_rs[nhalf][lrow[s2]] = v;
        }
#pragma unroll
        for (int j = 0; j < 2; j++)
#pragma unroll
            for (int cb = 0; cb < 2; cb++) {
                float v = qcs[j][cb];
                v += __shfl_xor_sync(0xffffffffu, v, 4);
                v += __shfl_xor_sync(0xffffffffu, v, 8);
                v += __shfl_xor_sync(0xffffffffu, v, 16);
                if (lane < 4)
                    s_cs[mwarp][nhalf * 16 + j * 8 + lane * 2 + cb] = v;
            }
        __syncthreads();
        if (tid < BM) {
            int slot = (qq == 0) ? qJ : 64 + (qJ - 56) * 3 + (qq - 1);
            g_p[((size_t)32 * BM + tid) * PSTRIDE + slot] =
                s_rs[0][tid] + s_rs[1][tid];
        }
        if (tid < 32) {
            g_p[((size_t)qJ * BM + qq * 32 + tid) * PSTRIDE + 32] =
                (s_cs[0][tid] + s_cs[1][tid]) + (s_cs[2][tid] + s_cs[3][tid]);
        }
    }

    // ================= TAIL: sim-complete arrive + inline reduce ===========
    __threadfence();
    __syncthreads();
    __shared__ int s_go;
    if (tid == 0) {
        atomicAdd(&g_done, 1);
        if (cta < 64) {
            while (*(volatile int*)&g_done < NCTA)
                asm volatile("nanosleep.u32 64;");
            s_go = 1;
        }
    }
    if (cta >= 64) return;
    __syncthreads();
    __threadfence();
    (void)s_go;

    // ---- reduce rowblock R = cta (256 threads; q<128 carry data) ----
    {
        int R = cta, q = tid;
        float lv = 0.f;
        if (q < 128) {
            int r = R * 128 + q;
            const float4* pp =
                reinterpret_cast<const float4*>(g_p + (size_t)r * PSTRIDE);
            float t0 = 0.f, t1 = 0.f, t2 = 0.f, t3 = 0.f;
#pragma unroll
            for (int i = 0; i < PSTRIDE / 4; i++) {
                float4 v = pp[i];
                t0 += v.x; t1 += v.y; t2 += v.z; t3 += v.w;
            }
            float tot = (t0 + t1) + (t2 + t3);
            tot -= ex2f(g_cdd[r] * L2E2);    // remove self term bit-exactly
            lv = logf(tot) - 2.0f * g_cdp[r];
        }
#pragma unroll
        for (int o = 16; o; o >>= 1) lv += __shfl_xor_sync(0xffffffffu, lv, o);
        __shared__ float w[8];
        __shared__ int slast;
        __shared__ float aa[2];
        if (lane == 0) w[wid] = lv;
        __syncthreads();
        if (tid == 0) {
            g_bs[R] = (w[0] + w[1]) + (w[2] + w[3]);   // warps 4-7 carry 0
            __threadfence();
            slast = (atomicAdd(&g_cnt, 1) == 63);
        }
        __syncthreads();
        if (slast) {
            __threadfence();
            if (tid < 64) {
                float v2 = g_bs[tid];
#pragma unroll
                for (int o = 16; o; o >>= 1)
                    v2 += __shfl_xor_sync(0xffffffffu, v2, o);
                if ((tid & 31) == 0) aa[tid >> 5] = v2;
            }
            __syncthreads();
            if (tid == 0) {
                out[0] = (aa[0] + aa[1]) / (float)TWO_N;
                g_cnt = 0;                   // reset for graph replay
                g_done = 0;                  // safe: all 64 reducers passed spin
            }
        }
    }
}

// ---------------------------------------------------------------------------
extern "C" void kernel_launch(void* const* d_in, const int* in_sizes, int n_in,
                              void* d_out, int out_size) {
    const float* z1 = (const float*)d_in[0];
    const float* z2 = (const float*)d_in[1];
    float* out = (float*)d_out;

    norm_kernel<<<TWO_N / 16, 256>>>(z1, z2);

    size_t smem = 3 * TILE_BYTES + 1024;   // 197,632 B
    cudaFuncSetAttribute(sim_kernel, cudaFuncAttributeMaxDynamicSharedMemorySize,
                         (int)smem);
    sim_kernel<<<NCTA, NTHR, smem>>>(out);
}

// round 17
// speedup vs baseline: 1.0102x; 1.0102x over previous
#include <cuda_runtime.h>
#include <cuda_bf16.h>
#include <cstdint>

#define TWO_N 8192
#define NHALF 4096
#define DDIM  256
#define BM 128
#define NCTA 148
#define NTHR 256             // 8 warps: 4(M) x 2(N), warp tile 32x64
#define CHUNK_BYTES 16384    // one [128 rows][128B] swizzled k-chunk
#define TILE_BYTES  65536    // 128 x 256 bf16
#define PSTRIDE 88           // per-row partial slots (64 main + 24 quarter)

__device__ __nv_bfloat16 g_znb[TWO_N * DDIM];
__device__ float g_p[(size_t)TWO_N * PSTRIDE];  // [row][88] partial exp-sums
__device__ float g_cdd[TWO_N];              // self dot per row
__device__ float g_cdp[TWO_N];              // positive-pair dot per row
__device__ float g_bs[64];                  // per-rowblock loss partial
__device__ int   g_cnt;                     // last-block counter

#define L2E2 2.8853900817779268f    /* 2/ln2 : exp(2d) = 2^(d*L2E2) */

// ---------------------------------------------------------------- helpers --
__device__ __forceinline__ uint32_t smem_u32(const void* p) {
    uint32_t a;
    asm("{ .reg .u64 t; cvta.to.shared.u64 t, %1; cvt.u32.u64 %0, t; }"
        : "=r"(a) : "l"(p));
    return a;
}
__device__ __forceinline__ float ex2f(float x) {
    float y; asm("ex2.approx.f32 %0, %1;" : "=f"(y) : "f"(x)); return y;
}
#define CP_ASYNC16(sm, gp) \
    asm volatile("cp.async.cg.shared.global [%0], [%1], 16;" \
                 :: "r"(sm), "l"(gp) : "memory")
#define CP_COMMIT()  asm volatile("cp.async.commit_group;" ::: "memory")
#define CP_WAIT(n)   asm volatile("cp.async.wait_group %0;" :: "n"(n) : "memory")

__device__ __forceinline__ void ldsm_x4(uint32_t* r, uint32_t addr) {
    asm volatile("ldmatrix.sync.aligned.m8n8.x4.shared.b16 {%0,%1,%2,%3}, [%4];"
                 : "=r"(r[0]), "=r"(r[1]), "=r"(r[2]), "=r"(r[3]) : "r"(addr));
}
__device__ __forceinline__ void mma16816(float* c, const uint32_t* a,
                                         uint32_t b0, uint32_t b1) {
    asm volatile(
        "mma.sync.aligned.m16n8k16.row.col.f32.bf16.bf16.f32 "
        "{%0,%1,%2,%3}, {%4,%5,%6,%7}, {%8,%9}, {%0,%1,%2,%3};"
        : "+f"(c[0]), "+f"(c[1]), "+f"(c[2]), "+f"(c[3])
        : "r"(a[0]), "r"(a[1]), "r"(a[2]), "r"(a[3]), "r"(b0), "r"(b1));
}

// upper-triangle block decode in paired-strip order
__device__ __forceinline__ void bdecode(int g, int& I, int& J) {
    int p = g / 65, r = g - p * 65;
    if (r < 64 - p) { I = p;      J = p + r; }
    else            { I = 63 - p; J = I + (r - (64 - p)); }
}

// ---------------------------------------------------------------------------
// Kernel 1: L2-normalize rows -> bf16. 2 rows per warp; block=128, grid=1024
// for finer SM spread (latency-bound kernel).
// ---------------------------------------------------------------------------
__global__ void norm_kernel(const float* __restrict__ z1,
                            const float* __restrict__ z2) {
    int wid = threadIdx.x >> 5, lane = threadIdx.x & 31;
    int row0 = (blockIdx.x * 4 + wid) * 2;
    int row1 = row0 + 1;
    const float4* s0 = reinterpret_cast<const float4*>(
        (row0 < NHALF) ? (z1 + (size_t)row0 * DDIM)
                       : (z2 + (size_t)(row0 - NHALF) * DDIM));
    const float4* s1 = reinterpret_cast<const float4*>(
        (row1 < NHALF) ? (z1 + (size_t)row1 * DDIM)
                       : (z2 + (size_t)(row1 - NHALF) * DDIM));
    float4 a0 = s0[lane * 2], a1 = s0[lane * 2 + 1];
    float4 b0 = s1[lane * 2], b1 = s1[lane * 2 + 1];
    float sa = a0.x * a0.x + a0.y * a0.y + a0.z * a0.z + a0.w * a0.w
             + a1.x * a1.x + a1.y * a1.y + a1.z * a1.z + a1.w * a1.w;
    float sb = b0.x * b0.x + b0.y * b0.y + b0.z * b0.z + b0.w * b0.w
             + b1.x * b1.x + b1.y * b1.y + b1.z * b1.z + b1.w * b1.w;
#pragma unroll
    for (int o = 16; o; o >>= 1) {
        sa += __shfl_xor_sync(0xffffffffu, sa, o);
        sb += __shfl_xor_sync(0xffffffffu, sb, o);
    }
    float ia = 1.0f / fmaxf(sqrtf(sa), 1e-8f);
    float ib = 1.0f / fmaxf(sqrtf(sb), 1e-8f);
    uint4 pa, pb;
    asm("cvt.rn.bf16x2.f32 %0, %1, %2;" : "=r"(pa.x) : "f"(a0.y * ia), "f"(a0.x * ia));
    asm("cvt.rn.bf16x2.f32 %0, %1, %2;" : "=r"(pa.y) : "f"(a0.w * ia), "f"(a0.z * ia));
    asm("cvt.rn.bf16x2.f32 %0, %1, %2;" : "=r"(pa.z) : "f"(a1.y * ia), "f"(a1.x * ia));
    asm("cvt.rn.bf16x2.f32 %0, %1, %2;" : "=r"(pa.w) : "f"(a1.w * ia), "f"(a1.z * ia));
    asm("cvt.rn.bf16x2.f32 %0, %1, %2;" : "=r"(pb.x) : "f"(b0.y * ib), "f"(b0.x * ib));
    asm("cvt.rn.bf16x2.f32 %0, %1, %2;" : "=r"(pb.y) : "f"(b0.w * ib), "f"(b0.z * ib));
    asm("cvt.rn.bf16x2.f32 %0, %1, %2;" : "=r"(pb.z) : "f"(b1.y * ib), "f"(b1.x * ib));
    asm("cvt.rn.bf16x2.f32 %0, %1, %2;" : "=r"(pb.w) : "f"(b1.w * ib), "f"(b1.z * ib));
    reinterpret_cast<uint4*>(g_znb + (size_t)row0 * DDIM)[lane] = pa;
    reinterpret_cast<uint4*>(g_znb + (size_t)row1 * DDIM)[lane] = pb;
}

// ---------------------------------------------------------------------------
// tile loader: 128 rows x 256 bf16 -> swizzled k-chunks via cp.async
// ---------------------------------------------------------------------------
__device__ __forceinline__ void load_tile(uint32_t sdst, int rowblk, int tid) {
    const char* gsrc = (const char*)(g_znb + (size_t)rowblk * BM * DDIM);
#pragma unroll
    for (int i = 0; i < 16; i++) {
        int unit = i * NTHR + tid;           // row*32 + uu
        int row = unit >> 5, uu = unit & 31;
        uint32_t off = (uint32_t)(row * 128 + (uu & 7) * 16);
        off ^= (off >> 3) & 0x70;
        CP_ASYNC16(sdst + (uu >> 3) * CHUNK_BYTES + off, gsrc + unit * 16);
    }
}

// ---------------------------------------------------------------------------
// Kernel 2: symmetric HMMA GEMM. Every CTA does exactly 14 full blocks
// (g = 0..2071); the 8 tail blocks (I=32, J=56..63 — no captures) are split
// into 32 N=32 quarter-blocks handled by CTAs 0..31.
// ---------------------------------------------------------------------------
__global__ void __launch_bounds__(NTHR, 1) sim_kernel() {
    extern __shared__ char smem_raw[];
    char* sbase = (char*)(((uintptr_t)smem_raw + 1023) & ~(uintptr_t)1023);
    uint32_t sAu = smem_u32(sbase);              // A: 64 KB (single)
    uint32_t sBu = sAu + TILE_BYTES;             // B: 2 x 64 KB

    __shared__ float s_rs[2][BM];                // n-half rowsum partials
    __shared__ float s_cs[8][64];                // [mwarp*2+nhalf][col]

    int tid = threadIdx.x;
    int wid = tid >> 5, lane = tid & 31;
    int cta = blockIdx.x;
    int start = cta * 14;
    const int cnt = 14;

    int m_base = (wid >> 1) * 32;
    int n_base = (wid & 1) * 64;
    int mwarp = wid >> 1, nhalf = wid & 1;

    // ---- per-lane ldmatrix address pieces ----
    int rA0 = m_base + (lane & 15);
    int rA1 = rA0 + 16;
    uint32_t kaddA = ((lane >> 4) & 1) * 16;
    uint32_t rowA0 = (uint32_t)rA0 * 128, xA0 = (uint32_t)(rA0 & 7) << 4;
    uint32_t rowA1 = (uint32_t)rA1 * 128, xA1 = (uint32_t)(rA1 & 7) << 4;
    int rBb = n_base + (lane & 7) + ((lane & 16) >> 1);
    uint32_t kaddB = ((lane >> 3) & 1) * 16;
    uint32_t rowB[4], xB[4];
#pragma unroll
    for (int gI = 0; gI < 4; gI++) {
        int r = rBb + gI * 16;
        rowB[gI] = (uint32_t)r * 128;
        xB[gI] = (uint32_t)(r & 7) << 4;
    }
    int lrow[4];
#pragma unroll
    for (int s = 0; s < 4; s++)
        lrow[s] = m_base + (s >> 1) * 16 + (lane >> 2) + (s & 1) * 8;
    int lcb = n_base + (lane & 3) * 2;           // base local col of this lane

    float accA[2][8][4], accB[2][8][4];
    float rs[4] = {0.f, 0.f, 0.f, 0.f};
    float cs[8][2];
#pragma unroll
    for (int j = 0; j < 8; j++) { cs[j][0] = 0.f; cs[j][1] = 0.f; }
    int curI;

    auto flush_old = [&](int oI, int oJ) {
#pragma unroll
        for (int s2 = 0; s2 < 4; s2++) {
            float v = rs[s2];
            v += __shfl_xor_sync(0xffffffffu, v, 1);
            v += __shfl_xor_sync(0xffffffffu, v, 2);
            if ((lane & 3) == 0) s_rs[nhalf][lrow[s2]] = v;
        }
        if (oI != oJ) {
#pragma unroll
            for (int j = 0; j < 8; j++)
#pragma unroll
                for (int cb = 0; cb < 2; cb++) {
                    float v = cs[j][cb];
                    v += __shfl_xor_sync(0xffffffffu, v, 4);
                    v += __shfl_xor_sync(0xffffffffu, v, 8);
                    v += __shfl_xor_sync(0xffffffffu, v, 16);
                    if (lane < 4)
                        s_cs[mwarp * 2 + nhalf][j * 8 + lane * 2 + cb] = v;
                }
        }
        __syncthreads();
        if (tid < BM) {
            g_p[((size_t)oI * BM + tid) * PSTRIDE + oJ] =
                s_rs[0][tid] + s_rs[1][tid];
            if (oI != oJ) {
                int nh = tid >> 6, cc = tid & 63;
                g_p[((size_t)oJ * BM + tid) * PSTRIDE + oI] =
                    s_cs[nh][cc] + s_cs[2 + nh][cc] +
                    s_cs[4 + nh][cc] + s_cs[6 + nh][cc];
            }
        }
#pragma unroll
        for (int s2 = 0; s2 < 4; s2++) rs[s2] = 0.f;
#pragma unroll
        for (int j = 0; j < 8; j++) { cs[j][0] = 0.f; cs[j][1] = 0.f; }
    };

    auto run_block = [&](float (&acc)[2][8][4], float (&aold)[2][8][4],
                         int n, int oI, int oJ, bool do_old) {
        if (n + 1 < cnt) {
            int In, Jn; bdecode(start + n + 1, In, Jn);
            load_tile(sBu + ((n + 1) & 1) * TILE_BYTES, Jn, tid);
            CP_COMMIT();
            CP_WAIT(1);
        } else {
            CP_WAIT(0);
        }
        __syncthreads();

#pragma unroll
        for (int i = 0; i < 2; i++)
#pragma unroll
            for (int j = 0; j < 8; j++)
#pragma unroll
                for (int q = 0; q < 4; q++) acc[i][j][q] = 0.f;

        uint32_t bbase = sBu + (n & 1) * TILE_BYTES;
        bool isdiag = (oI == oJ);
        bool capb = do_old && (isdiag || oJ == oI + 32);

#pragma unroll
        for (int s = 0; s < 16; s++) {           // k = s*16
            uint32_t coff = (uint32_t)(s >> 2) * CHUNK_BYTES;
            uint32_t kbA = (uint32_t)(s & 3) * 32 + kaddA;
            uint32_t kbB = (uint32_t)(s & 3) * 32 + kaddB;
            uint32_t a0[4], a1[4], b[4][4];
            ldsm_x4(a0, sAu + coff + rowA0 + (kbA ^ xA0));
            ldsm_x4(a1, sAu + coff + rowA1 + (kbA ^ xA1));
#pragma unroll
            for (int gI = 0; gI < 4; gI++)
                ldsm_x4(b[gI], bbase + coff + rowB[gI] + (kbB ^ xB[gI]));

            // deferred epilogue chunk: element (ii, jj) of old block
            if (do_old) {
                const int ii = s >> 3, jj = s & 7;
#pragma unroll
                for (int q = 0; q < 4; q++) {
                    float d = aold[ii][jj][q];
                    float e = ex2f(d * L2E2);
                    rs[ii * 2 + (q >> 1)] += e;
                    cs[jj][q & 1] += e;
                    if (capb) {
                        int slot = ii * 2 + (q >> 1);
                        int lc = lcb + jj * 8 + (q & 1);
                        if (lc == lrow[slot]) {
                            int rg = oI * BM + lrow[slot];
                            if (isdiag) g_cdd[rg] = d;
                            else { g_cdp[rg] = d;
                                   g_cdp[oJ * BM + lrow[slot]] = d; }
                        }
                    }
                }
            }

#pragma unroll
            for (int j = 0; j < 8; j++) {
                uint32_t b0 = b[j >> 1][(j & 1) * 2];
                uint32_t b1 = b[j >> 1][(j & 1) * 2 + 1];
                mma16816(acc[0][j], a0, b0, b1);
                mma16816(acc[1][j], a1, b0, b1);
            }
        }
        __syncthreads();   // sA / sB[n&1] no longer read

        if (n + 1 < cnt) {
            int In, Jn; bdecode(start + n + 1, In, Jn);
            if (In != curI) { load_tile(sAu, In, tid); CP_COMMIT(); curI = In; }
        }
        if (do_old) flush_old(oI, oJ);
    };

    // ---- prologue ----
    int I0, J0; bdecode(start, I0, J0);
    load_tile(sAu, I0, tid); CP_COMMIT();
    load_tile(sBu, J0, tid); CP_COMMIT();
    curI = I0;

    bool useA = true;
    int pI = 0, pJ = 0;
#pragma unroll 1
    for (int n = 0; n < cnt; n++) {
        int I, J; bdecode(start + n, I, J);
        if (useA) run_block(accA, accB, n, pI, pJ, n > 0);
        else      run_block(accB, accA, n, pI, pJ, n > 0);
        useA = !useA; pI = I; pJ = J;
    }

    // ---- issue quarter-block loads early (overlap final epilogue) ----
    int qJ = 56 + (cta >> 2);
    if (cta < 32) {
        load_tile(sAu, 32, tid);
        load_tile(sBu, qJ, tid);
        CP_COMMIT();
    }

    // ---- final (non-interleaved) epilogue for the last full block ----
    {
        __syncthreads();
        bool isdiag = (pI == pJ);
        bool capb = isdiag || (pJ == pI + 32);
#pragma unroll
        for (int ii = 0; ii < 2; ii++)
#pragma unroll
            for (int jj = 0; jj < 8; jj++)
#pragma unroll
                for (int q = 0; q < 4; q++) {
                    float d = useA ? accB[ii][jj][q] : accA[ii][jj][q];
                    float e = ex2f(d * L2E2);
                    rs[ii * 2 + (q >> 1)] += e;
                    cs[jj][q & 1] += e;
                    if (capb) {
                        int slot = ii * 2 + (q >> 1);
                        int lc = lcb + jj * 8 + (q & 1);
                        if (lc == lrow[slot]) {
                            int rg = pI * BM + lrow[slot];
                            if (isdiag) g_cdd[rg] = d;
                            else { g_cdp[rg] = d;
                                   g_cdp[pJ * BM + lrow[slot]] = d; }
                        }
                    }
                }
        flush_old(pI, pJ);
    }

    // ---- quarter-block (CTAs 0..31): N=32 slice of block (32, qJ) ----
    if (cta < 32) {
        int qq = cta & 3;
        CP_WAIT(0);
        __syncthreads();

        int colbase = qq * 32 + nhalf * 16;      // quarter col base per n-warp
        int rBq = colbase + (lane & 7) + ((lane & 16) >> 1);
        uint32_t rowBq = (uint32_t)rBq * 128, xBq = (uint32_t)(rBq & 7) << 4;

        float qacc[2][2][4];
#pragma unroll
        for (int i = 0; i < 2; i++)
#pragma unroll
            for (int j = 0; j < 2; j++)
#pragma unroll
                for (int q = 0; q < 4; q++) qacc[i][j][q] = 0.f;

#pragma unroll
        for (int s = 0; s < 16; s++) {           // k = s*16
            uint32_t coff = (uint32_t)(s >> 2) * CHUNK_BYTES;
            uint32_t kbA = (uint32_t)(s & 3) * 32 + kaddA;
            uint32_t kbB = (uint32_t)(s & 3) * 32 + kaddB;
            uint32_t a0[4], a1[4], bq[4];
            ldsm_x4(a0, sAu + coff + rowA0 + (kbA ^ xA0));
            ldsm_x4(a1, sAu + coff + rowA1 + (kbA ^ xA1));
            ldsm_x4(bq, sBu + coff + rowBq + (kbB ^ xBq));
            mma16816(qacc[0][0], a0, bq[0], bq[1]);
            mma16816(qacc[0][1], a0, bq[2], bq[3]);
            mma16816(qacc[1][0], a1, bq[0], bq[1]);
            mma16816(qacc[1][1], a1, bq[2], bq[3]);
        }

        // epilogue: rowsums + colsums (no captures possible here)
        float qrs[4] = {0.f, 0.f, 0.f, 0.f};
        float qcs[2][2] = {{0.f, 0.f}, {0.f, 0.f}};
#pragma unroll
        for (int ii = 0; ii < 2; ii++)
#pragma unroll
            for (int jj = 0; jj < 2; jj++)
#pragma unroll
                for (int q = 0; q < 4; q++) {
                    float e = ex2f(qacc[ii][jj][q] * L2E2);
                    qrs[ii * 2 + (q >> 1)] += e;
                    qcs[jj][q & 1] += e;
                }
#pragma unroll
        for (int s2 = 0; s2 < 4; s2++) {
            float v = qrs[s2];
            v += __shfl_xor_sync(0xffffffffu, v, 1);
            v += __shfl_xor_sync(0xffffffffu, v, 2);
            if ((lane & 3) == 0) s_rs[nhalf][lrow[s2]] = v;
        }
#pragma unroll
        for (int j = 0; j < 2; j++)
#pragma unroll
            for (int cb = 0; cb < 2; cb++) {
                float v = qcs[j][cb];
                v += __shfl_xor_sync(0xffffffffu, v, 4);
                v += __shfl_xor_sync(0xffffffffu, v, 8);
                v += __shfl_xor_sync(0xffffffffu, v, 16);
                if (lane < 4)
                    s_cs[mwarp][nhalf * 16 + j * 8 + lane * 2 + cb] = v;
            }
        __syncthreads();
        if (tid < BM) {
            int slot = (qq == 0) ? qJ : 64 + (qJ - 56) * 3 + (qq - 1);
            g_p[((size_t)32 * BM + tid) * PSTRIDE + slot] =
                s_rs[0][tid] + s_rs[1][tid];
        }
        if (tid < 32) {
            g_p[((size_t)qJ * BM + qq * 32 + tid) * PSTRIDE + 32] =
                (s_cs[0][tid] + s_cs[1][tid]) + (s_cs[2][tid] + s_cs[3][tid]);
        }
    }
}

// ---------------------------------------------------------------------------
// Kernel 3: per-row combine (22 contiguous float4 reads) -> loss;
// last block does final mean.
// ---------------------------------------------------------------------------
__global__ void reduce_kernel(float* __restrict__ out) {
    int R = blockIdx.x, q = threadIdx.x;     // 64 blocks x 128 threads
    int r = R * 128 + q;

    const float4* pp = reinterpret_cast<const float4*>(g_p + (size_t)r * PSTRIDE);
    float t0 = 0.f, t1 = 0.f, t2 = 0.f, t3 = 0.f;
#pragma unroll
    for (int i = 0; i < PSTRIDE / 4; i++) {
        float4 v = pp[i];
        t0 += v.x; t1 += v.y; t2 += v.z; t3 += v.w;
    }
    float tot = (t0 + t1) + (t2 + t3);
    tot -= ex2f(g_cdd[r] * L2E2);            // remove self term bit-exactly
    float lv = logf(tot) - 2.0f * g_cdp[r];

    int lane = q & 31;
#pragma unroll
    for (int o = 16; o; o >>= 1) lv += __shfl_xor_sync(0xffffffffu, lv, o);
    __shared__ float w[4];
    __shared__ int slast;
    __shared__ float aa[2];
    if (lane == 0) w[q >> 5] = lv;
    __syncthreads();
    if (q == 0) {
        g_bs[R] = w[0] + w[1] + w[2] + w[3];
        __threadfence();
        slast = (atomicAdd(&g_cnt, 1) == 63);
    }
    __syncthreads();
    if (slast) {
        __threadfence();
        if (q < 64) {
            float v2 = g_bs[q];
#pragma unroll
            for (int o = 16; o; o >>= 1)
                v2 += __shfl_xor_sync(0xffffffffu, v2, o);
            if ((q & 31) == 0) aa[q >> 5] = v2;
        }
        __syncthreads();
        if (q == 0) {
            out[0] = (aa[0] + aa[1]) / (float)TWO_N;
            g_cnt = 0;                       // reset for graph replay
        }
    }
}

// ---------------------------------------------------------------------------
extern "C" void kernel_launch(void* const* d_in, const int* in_sizes, int n_in,
                              void* d_out, int out_size) {
    const float* z1 = (const float*)d_in[0];
    const float* z2 = (const float*)d_in[1];
    float* out = (float*)d_out;

    norm_kernel<<<TWO_N / 8, 128>>>(z1, z2);

    size_t smem = 3 * TILE_BYTES + 1024;   // 197,632 B
    cudaFuncSetAttribute(sim_kernel, cudaFuncAttributeMaxDynamicSharedMemorySize,
                         (int)smem);
    sim_kernel<<<NCTA, NTHR, smem>>>();

    reduce_kernel<<<64, 128>>>(out);
}